// round 1
// baseline (speedup 1.0000x reference)
#include <cuda_runtime.h>

#define BATCH 2
#define SEQ 2048
#define DMODEL 2048
#define NHEADS 16
#define HDIM 128
#define HHDIM 64

typedef unsigned long long ull;

// ---------------- scratch (device globals: no allocations allowed) -----------
__device__ float g_xq[BATCH * SEQ * NHEADS * HDIM];   // 33.5 MB
__device__ float g_xk[BATCH * SEQ * NHEADS * HDIM];
__device__ float g_xv[BATCH * SEQ * NHEADS * HDIM];
__device__ float g_attn[BATCH * SEQ * DMODEL];        // scrambled (b,h,s,d) layout
__device__ float g_lambda;

// ---------------- packed f32x2 helpers (ptxas never auto-fuses these) --------
__device__ __forceinline__ ull pk2(float lo, float hi) {
    ull r; asm("mov.b64 %0, {%1,%2};" : "=l"(r) : "f"(lo), "f"(hi)); return r;
}
__device__ __forceinline__ void ffma2(ull& d, ull a, ull b) {
    asm("fma.rn.f32x2 %0, %1, %2, %0;" : "+l"(d) : "l"(a), "l"(b));
}
__device__ __forceinline__ void fmul2(ull& d, ull b) {
    asm("mul.rn.f32x2 %0, %0, %1;" : "+l"(d) : "l"(b));
}
__device__ __forceinline__ float2 upk2(ull v) {
    float2 f; asm("mov.b64 {%0,%1}, %2;" : "=f"(f.x), "=f"(f.y) : "l"(v)); return f;
}

// ---------------- SGEMM: Y[M,N] = X[M,K] @ W[N,K]^T  (fp32, f32x2 packed) ----
#define GBM 128
#define GBN 128
#define GBK 16
#define GLD 132   // padded row stride in shared

__global__ __launch_bounds__(256, 2)
void sgemm_tn(const float* __restrict__ X, const float* __restrict__ W,
              float* __restrict__ Y, int M, int N, int K) {
    __shared__ __align__(16) float As[GBK][GLD];
    __shared__ __align__(16) float Bs[GBK][GLD];

    const int tid = threadIdx.x;
    const int tx = tid & 15, ty = tid >> 4;
    const int m0 = blockIdx.y * GBM, n0 = blockIdx.x * GBN;

    ull acc[8][4];
#pragma unroll
    for (int r = 0; r < 8; r++)
#pragma unroll
        for (int j = 0; j < 4; j++) acc[r][j] = 0ull;

    const int lrow = tid >> 1;         // 0..127
    const int lk = (tid & 1) * 8;      // 0 or 8
    const float* Xp = X + (long)(m0 + lrow) * K + lk;
    const float* Wp = W + (long)(n0 + lrow) * K + lk;

    for (int k0 = 0; k0 < K; k0 += GBK) {
        float4 xa = *(const float4*)(Xp + k0);
        float4 xb = *(const float4*)(Xp + k0 + 4);
        float4 wa = *(const float4*)(Wp + k0);
        float4 wb = *(const float4*)(Wp + k0 + 4);
        __syncthreads();
        As[lk + 0][lrow] = xa.x; As[lk + 1][lrow] = xa.y;
        As[lk + 2][lrow] = xa.z; As[lk + 3][lrow] = xa.w;
        As[lk + 4][lrow] = xb.x; As[lk + 5][lrow] = xb.y;
        As[lk + 6][lrow] = xb.z; As[lk + 7][lrow] = xb.w;
        Bs[lk + 0][lrow] = wa.x; Bs[lk + 1][lrow] = wa.y;
        Bs[lk + 2][lrow] = wa.z; Bs[lk + 3][lrow] = wa.w;
        Bs[lk + 4][lrow] = wb.x; Bs[lk + 5][lrow] = wb.y;
        Bs[lk + 6][lrow] = wb.z; Bs[lk + 7][lrow] = wb.w;
        __syncthreads();
#pragma unroll
        for (int k = 0; k < GBK; k++) {
            float4 a0 = *(const float4*)&As[k][ty * 4];
            float4 a1 = *(const float4*)&As[k][64 + ty * 4];
            ull b0 = *(const ull*)&Bs[k][tx * 4];
            ull b1 = *(const ull*)&Bs[k][tx * 4 + 2];
            ull b2 = *(const ull*)&Bs[k][64 + tx * 4];
            ull b3 = *(const ull*)&Bs[k][64 + tx * 4 + 2];
            float av[8] = {a0.x, a0.y, a0.z, a0.w, a1.x, a1.y, a1.z, a1.w};
#pragma unroll
            for (int r = 0; r < 8; r++) {
                ull a2 = pk2(av[r], av[r]);
                ffma2(acc[r][0], a2, b0);
                ffma2(acc[r][1], a2, b1);
                ffma2(acc[r][2], a2, b2);
                ffma2(acc[r][3], a2, b3);
            }
        }
    }
#pragma unroll
    for (int r = 0; r < 8; r++) {
        int m = m0 + ((r < 4) ? (ty * 4 + r) : (64 + ty * 4 + (r - 4)));
        float* yp = Y + (long)m * N + n0;
        float2 c0 = upk2(acc[r][0]), c1 = upk2(acc[r][1]);
        float2 c2 = upk2(acc[r][2]), c3 = upk2(acc[r][3]);
        *(float2*)(yp + tx * 4) = c0;
        *(float2*)(yp + tx * 4 + 2) = c1;
        *(float2*)(yp + 64 + tx * 4) = c2;
        *(float2*)(yp + 64 + tx * 4 + 2) = c3;
    }
}

// ---------------- RoPE (in-place on g_xq / g_xk) -----------------------------
__global__ void rope_kernel(const float* __restrict__ fc) {
    int idx = blockIdx.x * blockDim.x + threadIdx.x;   // pair index
    const int NP = BATCH * SEQ * NHEADS * HHDIM;       // 4,194,304
    if (idx >= NP) return;
    float* buf = blockIdx.y ? g_xk : g_xq;
    int d2 = idx & 63;
    int h  = (idx >> 6) & 15;
    int s  = (idx >> 10) & 2047;
    int b  = idx >> 21;
    float* p = buf + (((b * SEQ + s) * NHEADS + h) << 7) + d2 * 2;
    const float* f = fc + s * 256 + d2 * 4;  // [cos, -sin, sin, cos]
    float e = p[0], o = p[1];
    p[0] = e * f[0] + o * f[1];
    p[1] = e * f[2] + o * f[3];
}

// ---------------- lambda scalar ---------------------------------------------
__global__ void lambda_kernel(const float* __restrict__ lq1, const float* __restrict__ lk1,
                              const float* __restrict__ lq2, const float* __restrict__ lk2) {
    int t = threadIdx.x;  // 32 threads
    float s1 = lq1[t] * lk1[t] + lq1[t + 32] * lk1[t + 32];
    float s2 = lq2[t] * lk2[t] + lq2[t + 32] * lk2[t + 32];
#pragma unroll
    for (int o = 16; o; o >>= 1) {
        s1 += __shfl_xor_sync(0xffffffffu, s1, o);
        s2 += __shfl_xor_sync(0xffffffffu, s2, o);
    }
    if (t == 0) g_lambda = expf(s1) - expf(s2) + 0.2f;
}

// ---------------- differential flash attention ------------------------------
// Block = (q-tile of 64, b*16+h). 512 threads: tx=tid&15, ty=tid>>4 (0..31).
// Thread owns rows {ty, ty+32}, S-cols {tx+16c}, O-cols {2tx+32cc, +1}.
#define FPAD 132
#define PPAD 68
#define FSM_FLOATS (3 * 64 * FPAD + 2 * 64 * PPAD)   // 34048 floats = 136192 B

__global__ __launch_bounds__(512, 1)
void flash_diff(const float* __restrict__ subln) {
    extern __shared__ __align__(16) float sm[];
    float* Qs  = sm;
    float* Ks  = sm + 64 * FPAD;
    float* Vs  = sm + 2 * 64 * FPAD;
    float* Ps1 = sm + 3 * 64 * FPAD;
    float* Ps2 = Ps1 + 64 * PPAD;

    const int tid = threadIdx.x;
    const int tx = tid & 15, ty = tid >> 4;
    const int qt = blockIdx.x, bh = blockIdx.y;
    const int b = bh >> 4, h = bh & 15;
    const int base = (b * SEQ * NHEADS + h) * HDIM;   // row stride = NHEADS*HDIM = 2048
    const float* Qg = g_xq + base;
    const float* Kg = g_xk + base;
    const float* Vg = g_xv + base;
    const int qs0 = qt * 64;
    const float lam = g_lambda;

    // load Q tile, pre-scaled by 1/sqrt(64)
    for (int i = tid; i < 2048; i += 512) {
        int row = i >> 5, d4 = (i & 31) << 2;
        float4 v = *(const float4*)(Qg + (qs0 + row) * 2048 + d4);
        v.x *= 0.125f; v.y *= 0.125f; v.z *= 0.125f; v.w *= 0.125f;
        *(float4*)&Qs[row * FPAD + d4] = v;
    }

    float m1[2] = {-1e30f, -1e30f}, l1[2] = {0.f, 0.f};
    float m2[2] = {-1e30f, -1e30f}, l2[2] = {0.f, 0.f};
    ull o1[2][4], o2[2][4];
#pragma unroll
    for (int r = 0; r < 2; r++)
#pragma unroll
        for (int j = 0; j < 4; j++) { o1[r][j] = 0ull; o2[r][j] = 0ull; }

    for (int kt = 0; kt <= qt; kt++) {
        __syncthreads();
        for (int i = tid; i < 2048; i += 512) {
            int row = i >> 5, d4 = (i & 31) << 2;
            int gr = (kt * 64 + row) * 2048 + d4;
            *(float4*)&Ks[row * FPAD + d4] = *(const float4*)(Kg + gr);
            *(float4*)&Vs[row * FPAD + d4] = *(const float4*)(Vg + gr);
        }
        __syncthreads();

        // ---- S = Q K^T for both streams ----
        float s1r[2][4], s2r[2][4];
#pragma unroll
        for (int r = 0; r < 2; r++)
#pragma unroll
            for (int c = 0; c < 4; c++) { s1r[r][c] = 0.f; s2r[r][c] = 0.f; }

#pragma unroll
        for (int d4 = 0; d4 < 64; d4 += 4) {
            float4 qa[2], ka[4];
#pragma unroll
            for (int r = 0; r < 2; r++) qa[r] = *(const float4*)&Qs[(ty + 32 * r) * FPAD + d4];
#pragma unroll
            for (int c = 0; c < 4; c++) ka[c] = *(const float4*)&Ks[(tx + 16 * c) * FPAD + d4];
#pragma unroll
            for (int r = 0; r < 2; r++)
#pragma unroll
                for (int c = 0; c < 4; c++)
                    s1r[r][c] += qa[r].x * ka[c].x + qa[r].y * ka[c].y +
                                 qa[r].z * ka[c].z + qa[r].w * ka[c].w;
#pragma unroll
            for (int r = 0; r < 2; r++) qa[r] = *(const float4*)&Qs[(ty + 32 * r) * FPAD + 64 + d4];
#pragma unroll
            for (int c = 0; c < 4; c++) ka[c] = *(const float4*)&Ks[(tx + 16 * c) * FPAD + 64 + d4];
#pragma unroll
            for (int r = 0; r < 2; r++)
#pragma unroll
                for (int c = 0; c < 4; c++)
                    s2r[r][c] += qa[r].x * ka[c].x + qa[r].y * ka[c].y +
                                 qa[r].z * ka[c].z + qa[r].w * ka[c].w;
        }

        const bool diag = (kt == qt);
#pragma unroll
        for (int r = 0; r < 2; r++) {
            const int q = ty + 32 * r;
            if (diag) {
#pragma unroll
                for (int c = 0; c < 4; c++) {
                    if (tx + 16 * c > q) { s1r[r][c] = -1e30f; s2r[r][c] = -1e30f; }
                }
            }
            // stream 1 online softmax
            float mx = fmaxf(fmaxf(s1r[r][0], s1r[r][1]), fmaxf(s1r[r][2], s1r[r][3]));
#pragma unroll
            for (int o = 8; o; o >>= 1) mx = fmaxf(mx, __shfl_xor_sync(0xffffffffu, mx, o));
            float mn = fmaxf(m1[r], mx);
            float corr = __expf(m1[r] - mn);
            float p[4], psum = 0.f;
#pragma unroll
            for (int c = 0; c < 4; c++) { p[c] = __expf(s1r[r][c] - mn); psum += p[c]; }
#pragma unroll
            for (int o = 8; o; o >>= 1) psum += __shfl_xor_sync(0xffffffffu, psum, o);
            l1[r] = l1[r] * corr + psum;
            m1[r] = mn;
            {
                ull cd = pk2(corr, corr);
#pragma unroll
                for (int j = 0; j < 4; j++) fmul2(o1[r][j], cd);
            }
#pragma unroll
            for (int c = 0; c < 4; c++) Ps1[q * PPAD + tx + 16 * c] = p[c];

            // stream 2 online softmax
            mx = fmaxf(fmaxf(s2r[r][0], s2r[r][1]), fmaxf(s2r[r][2], s2r[r][3]));
#pragma unroll
            for (int o = 8; o; o >>= 1) mx = fmaxf(mx, __shfl_xor_sync(0xffffffffu, mx, o));
            mn = fmaxf(m2[r], mx);
            corr = __expf(m2[r] - mn);
            psum = 0.f;
#pragma unroll
            for (int c = 0; c < 4; c++) { p[c] = __expf(s2r[r][c] - mn); psum += p[c]; }
#pragma unroll
            for (int o = 8; o; o >>= 1) psum += __shfl_xor_sync(0xffffffffu, psum, o);
            l2[r] = l2[r] * corr + psum;
            m2[r] = mn;
            {
                ull cd = pk2(corr, corr);
#pragma unroll
                for (int j = 0; j < 4; j++) fmul2(o2[r][j], cd);
            }
#pragma unroll
            for (int c = 0; c < 4; c++) Ps2[q * PPAD + tx + 16 * c] = p[c];
        }
        __syncthreads();

        // ---- O += P V (both streams share V), packed f32x2 ----
#pragma unroll 4
        for (int n = 0; n < 64; n++) {
            const float* vrow = &Vs[n * FPAD + 2 * tx];
            ull v0 = *(const ull*)(vrow);
            ull v1 = *(const ull*)(vrow + 32);
            ull v2 = *(const ull*)(vrow + 64);
            ull v3 = *(const ull*)(vrow + 96);
#pragma unroll
            for (int r = 0; r < 2; r++) {
                const int q = ty + 32 * r;
                float p1 = Ps1[q * PPAD + n];
                float p2 = Ps2[q * PPAD + n];
                ull p1d = pk2(p1, p1), p2d = pk2(p2, p2);
                ffma2(o1[r][0], p1d, v0); ffma2(o1[r][1], p1d, v1);
                ffma2(o1[r][2], p1d, v2); ffma2(o1[r][3], p1d, v3);
                ffma2(o2[r][0], p2d, v0); ffma2(o2[r][1], p2d, v1);
                ffma2(o2[r][2], p2d, v2); ffma2(o2[r][3], p2d, v3);
            }
        }
    }

    // ---- epilogue: diff, RMSNorm(128), subln_w, *(1-LAMBDA_INIT), scrambled store
#pragma unroll
    for (int r = 0; r < 2; r++) {
        float inv1 = 1.0f / l1[r];
        float sc2 = lam / l2[r];
        float cv8[8];
        float ss = 0.f;
#pragma unroll
        for (int cc = 0; cc < 4; cc++) {
            float2 a = upk2(o1[r][cc]);
            float2 bb = upk2(o2[r][cc]);
            float u = a.x * inv1 - bb.x * sc2;
            float w = a.y * inv1 - bb.y * sc2;
            cv8[2 * cc] = u; cv8[2 * cc + 1] = w;
            ss += u * u + w * w;
        }
#pragma unroll
        for (int o = 8; o; o >>= 1) ss += __shfl_xor_sync(0xffffffffu, ss, o);
        float rms = rsqrtf(ss * (1.0f / 128.0f) + 1e-5f);
        int sg = qs0 + ty + 32 * r;
        // (b,h,s,d) flat == scrambled (b, s', f) row-major
        float* op = g_attn + (long)b * (SEQ * DMODEL) + h * (SEQ * HDIM) + sg * HDIM;
#pragma unroll
        for (int cc = 0; cc < 4; cc++) {
            int cvx = 2 * tx + 32 * cc;
            float2 w2;
            w2.x = cv8[2 * cc] * rms * subln[cvx] * 0.8f;
            w2.y = cv8[2 * cc + 1] * rms * subln[cvx + 1] * 0.8f;
            *(float2*)(op + cvx) = w2;
        }
    }
}

// ---------------- launch -----------------------------------------------------
extern "C" void kernel_launch(void* const* d_in, const int* in_sizes, int n_in,
                              void* d_out, int out_size) {
    const float* x    = (const float*)d_in[0];
    const float* fc   = (const float*)d_in[1];
    const float* wq   = (const float*)d_in[2];
    const float* wk   = (const float*)d_in[3];
    const float* wv   = (const float*)d_in[4];
    const float* wo   = (const float*)d_in[5];
    const float* lq1  = (const float*)d_in[6];
    const float* lk1  = (const float*)d_in[7];
    const float* lq2  = (const float*)d_in[8];
    const float* lk2  = (const float*)d_in[9];
    const float* subw = (const float*)d_in[10];
    float* out = (float*)d_out;

    float *xq_p, *xk_p, *xv_p, *attn_p;
    cudaGetSymbolAddress((void**)&xq_p, g_xq);
    cudaGetSymbolAddress((void**)&xk_p, g_xk);
    cudaGetSymbolAddress((void**)&xv_p, g_xv);
    cudaGetSymbolAddress((void**)&attn_p, g_attn);

    const int M = BATCH * SEQ;           // 4096
    dim3 gg(DMODEL / GBN, M / GBM);      // (16, 32)

    sgemm_tn<<<gg, 256>>>(x, wq, xq_p, M, DMODEL, DMODEL);
    sgemm_tn<<<gg, 256>>>(x, wk, xk_p, M, DMODEL, DMODEL);
    sgemm_tn<<<gg, 256>>>(x, wv, xv_p, M, DMODEL, DMODEL);

    rope_kernel<<<dim3((BATCH * SEQ * NHEADS * HHDIM) / 256, 2), 256>>>(fc);
    lambda_kernel<<<1, 32>>>(lq1, lk1, lq2, lk2);

    static_assert(FSM_FLOATS * 4 == 136192, "smem size");
    cudaFuncSetAttribute(flash_diff, cudaFuncAttributeMaxDynamicSharedMemorySize,
                         FSM_FLOATS * 4);
    flash_diff<<<dim3(SEQ / 64, BATCH * NHEADS), 512, FSM_FLOATS * 4>>>(subw);

    sgemm_tn<<<gg, 256>>>(attn_p, wo, out, M, DMODEL, DMODEL);
}

// round 8
// speedup vs baseline: 1.4497x; 1.4497x over previous
#include <cuda_runtime.h>
#include <cuda_bf16.h>
#include <cstdint>

#define BATCH 2
#define SEQ 2048
#define DMODEL 2048
#define NHEADS 16
#define HDIM 128
#define HHDIM 64

typedef unsigned long long ull;

// ---------------- scratch (device globals: no allocations allowed) -----------
__device__ float g_xq[BATCH * SEQ * NHEADS * HDIM];
__device__ float g_xk[BATCH * SEQ * NHEADS * HDIM];
__device__ float g_xv[BATCH * SEQ * NHEADS * HDIM];
__device__ float g_attn[BATCH * SEQ * DMODEL];        // scrambled (b,h,s,d) layout
__device__ float g_lambda;

// bf16 split buffers
__device__ __nv_bfloat16 g_xhi[BATCH * SEQ * DMODEL];
__device__ __nv_bfloat16 g_xlo[BATCH * SEQ * DMODEL];
__device__ __nv_bfloat16 g_ahi[BATCH * SEQ * DMODEL];
__device__ __nv_bfloat16 g_alo[BATCH * SEQ * DMODEL];
__device__ __nv_bfloat16 g_whi[4][DMODEL * DMODEL];   // q,k,v,o
__device__ __nv_bfloat16 g_wlo[4][DMODEL * DMODEL];

// ---------------- packed f32x2 helpers ---------------------------------------
__device__ __forceinline__ ull pk2(float lo, float hi) {
    ull r; asm("mov.b64 %0, {%1,%2};" : "=l"(r) : "f"(lo), "f"(hi)); return r;
}
__device__ __forceinline__ void ffma2(ull& d, ull a, ull b) {
    asm("fma.rn.f32x2 %0, %1, %2, %0;" : "+l"(d) : "l"(a), "l"(b));
}
__device__ __forceinline__ void fmul2(ull& d, ull b) {
    asm("mul.rn.f32x2 %0, %0, %1;" : "+l"(d) : "l"(b));
}
__device__ __forceinline__ float2 upk2(ull v) {
    float2 f; asm("mov.b64 {%0,%1}, %2;" : "=f"(f.x), "=f"(f.y) : "l"(v)); return f;
}

// ---------------- warp-MMA / async-copy helpers (baseline PTX, no 'a' feats) -
__device__ __forceinline__ uint32_t smem_u32(const void* p) {
    uint32_t a;
    asm("{ .reg .u64 t; cvta.to.shared.u64 t, %1; cvt.u32.u64 %0, t; }" : "=r"(a) : "l"(p));
    return a;
}
__device__ __forceinline__ void ldsm4(uint32_t* r, uint32_t addr) {
    asm volatile("ldmatrix.sync.aligned.m8n8.x4.shared.b16 {%0,%1,%2,%3}, [%4];"
                 : "=r"(r[0]), "=r"(r[1]), "=r"(r[2]), "=r"(r[3]) : "r"(addr));
}
__device__ __forceinline__ void mma16816(float* c, const uint32_t* a,
                                         uint32_t b0, uint32_t b1) {
    asm volatile("mma.sync.aligned.m16n8k16.row.col.f32.bf16.bf16.f32 "
                 "{%0,%1,%2,%3}, {%4,%5,%6,%7}, {%8,%9}, {%0,%1,%2,%3};"
                 : "+f"(c[0]), "+f"(c[1]), "+f"(c[2]), "+f"(c[3])
                 : "r"(a[0]), "r"(a[1]), "r"(a[2]), "r"(a[3]), "r"(b0), "r"(b1));
}
__device__ __forceinline__ void cp16(uint32_t saddr, const void* g) {
    asm volatile("cp.async.cg.shared.global [%0], [%1], 16;" :: "r"(saddr), "l"(g));
}
__device__ __forceinline__ void cp_commit() { asm volatile("cp.async.commit_group;"); }
__device__ __forceinline__ void cp_wait1()  { asm volatile("cp.async.wait_group 1;" ::: "memory"); }
__device__ __forceinline__ void cp_wait0()  { asm volatile("cp.async.wait_group 0;" ::: "memory"); }

// ---------------- bf16 hi/lo split -------------------------------------------
__global__ void split_bf16(const float* __restrict__ src, __nv_bfloat16* __restrict__ hi,
                           __nv_bfloat16* __restrict__ lo, int n) {
    int i = (blockIdx.x * blockDim.x + threadIdx.x) * 4;
    if (i >= n) return;
    float4 v = *(const float4*)(src + i);
    __nv_bfloat16 h0 = __float2bfloat16(v.x), h1 = __float2bfloat16(v.y);
    __nv_bfloat16 h2 = __float2bfloat16(v.z), h3 = __float2bfloat16(v.w);
    __nv_bfloat16 l0 = __float2bfloat16(v.x - __bfloat162float(h0));
    __nv_bfloat16 l1 = __float2bfloat16(v.y - __bfloat162float(h1));
    __nv_bfloat16 l2 = __float2bfloat16(v.z - __bfloat162float(h2));
    __nv_bfloat16 l3 = __float2bfloat16(v.w - __bfloat162float(h3));
    uint2 hp, lp;
    hp.x = (uint32_t)__bfloat16_as_ushort(h0) | ((uint32_t)__bfloat16_as_ushort(h1) << 16);
    hp.y = (uint32_t)__bfloat16_as_ushort(h2) | ((uint32_t)__bfloat16_as_ushort(h3) << 16);
    lp.x = (uint32_t)__bfloat16_as_ushort(l0) | ((uint32_t)__bfloat16_as_ushort(l1) << 16);
    lp.y = (uint32_t)__bfloat16_as_ushort(l2) | ((uint32_t)__bfloat16_as_ushort(l3) << 16);
    *(uint2*)(hi + i) = hp;
    *(uint2*)(lo + i) = lp;
}

// ---------------- split-bf16 HMMA GEMM ---------------------------------------
// Y[4096, 2048] = A[4096, 2048] @ W[2048, 2048]^T via (hi+lo) bf16, 3 products.
// CTA 128x128, 8 warps (2M x 4N), warp tile 64x32. K chunk = 32. 3-stage cp.async.
#define TSTR 80                      // padded bytes per 32-bf16 row (bank-safe)
#define BUF_BYTES (128 * TSTR)       // 10240
#define STG_BYTES (4 * BUF_BYTES)    // Ahi,Alo,Bhi,Blo = 40960
#define NSTG 3
#define GEMM_SMEM (NSTG * STG_BYTES) // 122880
#define NCH (DMODEL / 32)            // 64 k-chunks

struct GemmB { const __nv_bfloat16* bhi; const __nv_bfloat16* blo; float* y; };

__global__ __launch_bounds__(256, 1)
void gemm_mma(const __nv_bfloat16* __restrict__ Ahi, const __nv_bfloat16* __restrict__ Alo,
              GemmB b0, GemmB b1, GemmB b2) {
    extern __shared__ char smem[];
    const uint32_t sb = smem_u32(smem);
    const int tid = threadIdx.x, wid = tid >> 5, lane = tid & 31;
    const int n0 = blockIdx.x * 128, m0 = blockIdx.y * 128;
    GemmB g = (blockIdx.z == 0) ? b0 : ((blockIdx.z == 1) ? b1 : b2);

    const __nv_bfloat16* srcs[4] = {
        Ahi + (size_t)m0 * DMODEL, Alo + (size_t)m0 * DMODEL,
        g.bhi + (size_t)n0 * DMODEL, g.blo + (size_t)n0 * DMODEL};

    // loader mapping: 512 16B-transfers per buffer, 2 per thread
    const int lrow0 = tid >> 2, lch = tid & 3;       // +64 rows for i=1

    float acc[4][4][4];
#pragma unroll
    for (int mt = 0; mt < 4; mt++)
#pragma unroll
        for (int nt = 0; nt < 4; nt++)
#pragma unroll
            for (int j = 0; j < 4; j++) acc[mt][nt][j] = 0.f;

    // prologue: stages 0,1
#pragma unroll
    for (int c = 0; c < 2; c++) {
        uint32_t stb = sb + c * STG_BYTES;
#pragma unroll
        for (int buf = 0; buf < 4; buf++) {
#pragma unroll
            for (int i = 0; i < 2; i++) {
                int row = lrow0 + i * 64;
                cp16(stb + buf * BUF_BYTES + row * TSTR + lch * 16,
                     srcs[buf] + (size_t)row * DMODEL + c * 32 + lch * 8);
            }
        }
        cp_commit();
    }

    const int wm = wid >> 2, wn = wid & 3;
    const int l7 = lane & 7, l8 = (lane >> 3) & 1, l16 = lane >> 4;
    // ldsm lane row/chunk offsets (within a 16-row tile, chunk pair base)
    const int lrow = l7 + l8 * 8;
    const int arow_base = wm * 64 + lrow;           // + mt*16
    const int brow_base = wn * 32 + lrow;           // + p*16

    for (int c = 0; c < NCH; c++) {
        if (c + 1 >= NCH) cp_wait0(); else cp_wait1();
        __syncthreads();
        // prefetch chunk c+2 into stage (c+2)%3
        if (c + 2 < NCH) {
            uint32_t stb = sb + ((c + 2) % NSTG) * STG_BYTES;
#pragma unroll
            for (int buf = 0; buf < 4; buf++) {
#pragma unroll
                for (int i = 0; i < 2; i++) {
                    int row = lrow0 + i * 64;
                    cp16(stb + buf * BUF_BYTES + row * TSTR + lch * 16,
                         srcs[buf] + (size_t)row * DMODEL + (c + 2) * 32 + lch * 8);
                }
            }
            cp_commit();
        }

        const uint32_t stb = sb + (c % NSTG) * STG_BYTES;
#pragma unroll
        for (int ks = 0; ks < 2; ks++) {
            const int ch = ks * 2 + l16;            // lane's 16B chunk
            uint32_t ahi[4][4], alo[4][4], bhi[2][4], blo[2][4];
#pragma unroll
            for (int mt = 0; mt < 4; mt++) {
                uint32_t off = (arow_base + mt * 16) * TSTR + ch * 16;
                ldsm4(ahi[mt], stb + 0 * BUF_BYTES + off);
                ldsm4(alo[mt], stb + 1 * BUF_BYTES + off);
            }
#pragma unroll
            for (int p = 0; p < 2; p++) {
                uint32_t off = (brow_base + p * 16) * TSTR + ch * 16;
                ldsm4(bhi[p], stb + 2 * BUF_BYTES + off);
                ldsm4(blo[p], stb + 3 * BUF_BYTES + off);
            }
#pragma unroll
            for (int mt = 0; mt < 4; mt++) {
#pragma unroll
                for (int nt = 0; nt < 4; nt++) {
                    const int p = nt >> 1, od = nt & 1;
                    mma16816(acc[mt][nt], ahi[mt], bhi[p][od], bhi[p][od + 2]);
                    mma16816(acc[mt][nt], ahi[mt], blo[p][od], blo[p][od + 2]);
                    mma16816(acc[mt][nt], alo[mt], bhi[p][od], bhi[p][od + 2]);
                }
            }
        }
        __syncthreads();
    }

    // epilogue
    const int erow = lane >> 2, ecol = (lane & 3) * 2;
#pragma unroll
    for (int mt = 0; mt < 4; mt++) {
#pragma unroll
        for (int nt = 0; nt < 4; nt++) {
            int rg = m0 + wm * 64 + mt * 16 + erow;
            int cg = n0 + wn * 32 + nt * 8 + ecol;
            *(float2*)(g.y + (size_t)rg * DMODEL + cg) =
                make_float2(acc[mt][nt][0], acc[mt][nt][1]);
            *(float2*)(g.y + (size_t)(rg + 8) * DMODEL + cg) =
                make_float2(acc[mt][nt][2], acc[mt][nt][3]);
        }
    }
}

// ---------------- RoPE (in-place on g_xq / g_xk) -----------------------------
__global__ void rope_kernel(const float* __restrict__ fc) {
    int idx = blockIdx.x * blockDim.x + threadIdx.x;
    const int NP = BATCH * SEQ * NHEADS * HHDIM;
    if (idx >= NP) return;
    float* buf = blockIdx.y ? g_xk : g_xq;
    int d2 = idx & 63;
    int h  = (idx >> 6) & 15;
    int s  = (idx >> 10) & 2047;
    int b  = idx >> 21;
    float* p = buf + (((b * SEQ + s) * NHEADS + h) << 7) + d2 * 2;
    const float* f = fc + s * 256 + d2 * 4;
    float e = p[0], o = p[1];
    p[0] = e * f[0] + o * f[1];
    p[1] = e * f[2] + o * f[3];
}

// ---------------- lambda scalar ---------------------------------------------
__global__ void lambda_kernel(const float* __restrict__ lq1, const float* __restrict__ lk1,
                              const float* __restrict__ lq2, const float* __restrict__ lk2) {
    int t = threadIdx.x;
    float s1 = lq1[t] * lk1[t] + lq1[t + 32] * lk1[t + 32];
    float s2 = lq2[t] * lk2[t] + lq2[t + 32] * lk2[t + 32];
#pragma unroll
    for (int o = 16; o; o >>= 1) {
        s1 += __shfl_xor_sync(0xffffffffu, s1, o);
        s2 += __shfl_xor_sync(0xffffffffu, s2, o);
    }
    if (t == 0) g_lambda = expf(s1) - expf(s2) + 0.2f;
}

// ---------------- differential flash attention (fp32, f32x2) -----------------
#define FPAD 132
#define PPAD 68
#define FSM_FLOATS (3 * 64 * FPAD + 2 * 64 * PPAD)

__global__ __launch_bounds__(512, 1)
void flash_diff(const float* __restrict__ subln) {
    extern __shared__ __align__(16) float sm[];
    float* Qs  = sm;
    float* Ks  = sm + 64 * FPAD;
    float* Vs  = sm + 2 * 64 * FPAD;
    float* Ps1 = sm + 3 * 64 * FPAD;
    float* Ps2 = Ps1 + 64 * PPAD;

    const int tid = threadIdx.x;
    const int tx = tid & 15, ty = tid >> 4;
    const int qt = blockIdx.x, bh = blockIdx.y;
    const int b = bh >> 4, h = bh & 15;
    const int base = (b * SEQ * NHEADS + h) * HDIM;
    const float* Qg = g_xq + base;
    const float* Kg = g_xk + base;
    const float* Vg = g_xv + base;
    const int qs0 = qt * 64;
    const float lam = g_lambda;

    for (int i = tid; i < 2048; i += 512) {
        int row = i >> 5, d4 = (i & 31) << 2;
        float4 v = *(const float4*)(Qg + (qs0 + row) * 2048 + d4);
        v.x *= 0.125f; v.y *= 0.125f; v.z *= 0.125f; v.w *= 0.125f;
        *(float4*)&Qs[row * FPAD + d4] = v;
    }

    float m1[2] = {-1e30f, -1e30f}, l1[2] = {0.f, 0.f};
    float m2[2] = {-1e30f, -1e30f}, l2[2] = {0.f, 0.f};
    ull o1[2][4], o2[2][4];
#pragma unroll
    for (int r = 0; r < 2; r++)
#pragma unroll
        for (int j = 0; j < 4; j++) { o1[r][j] = 0ull; o2[r][j] = 0ull; }

    for (int kt = 0; kt <= qt; kt++) {
        __syncthreads();
        for (int i = tid; i < 2048; i += 512) {
            int row = i >> 5, d4 = (i & 31) << 2;
            int gr = (kt * 64 + row) * 2048 + d4;
            *(float4*)&Ks[row * FPAD + d4] = *(const float4*)(Kg + gr);
            *(float4*)&Vs[row * FPAD + d4] = *(const float4*)(Vg + gr);
        }
        __syncthreads();

        float s1r[2][4], s2r[2][4];
#pragma unroll
        for (int r = 0; r < 2; r++)
#pragma unroll
            for (int c = 0; c < 4; c++) { s1r[r][c] = 0.f; s2r[r][c] = 0.f; }

#pragma unroll
        for (int d4 = 0; d4 < 64; d4 += 4) {
            float4 qa[2], ka[4];
#pragma unroll
            for (int r = 0; r < 2; r++) qa[r] = *(const float4*)&Qs[(ty + 32 * r) * FPAD + d4];
#pragma unroll
            for (int c = 0; c < 4; c++) ka[c] = *(const float4*)&Ks[(tx + 16 * c) * FPAD + d4];
#pragma unroll
            for (int r = 0; r < 2; r++)
#pragma unroll
                for (int c = 0; c < 4; c++)
                    s1r[r][c] += qa[r].x * ka[c].x + qa[r].y * ka[c].y +
                                 qa[r].z * ka[c].z + qa[r].w * ka[c].w;
#pragma unroll
            for (int r = 0; r < 2; r++) qa[r] = *(const float4*)&Qs[(ty + 32 * r) * FPAD + 64 + d4];
#pragma unroll
            for (int c = 0; c < 4; c++) ka[c] = *(const float4*)&Ks[(tx + 16 * c) * FPAD + 64 + d4];
#pragma unroll
            for (int r = 0; r < 2; r++)
#pragma unroll
                for (int c = 0; c < 4; c++)
                    s2r[r][c] += qa[r].x * ka[c].x + qa[r].y * ka[c].y +
                                 qa[r].z * ka[c].z + qa[r].w * ka[c].w;
        }

        const bool diag = (kt == qt);
#pragma unroll
        for (int r = 0; r < 2; r++) {
            const int q = ty + 32 * r;
            if (diag) {
#pragma unroll
                for (int c = 0; c < 4; c++) {
                    if (tx + 16 * c > q) { s1r[r][c] = -1e30f; s2r[r][c] = -1e30f; }
                }
            }
            float mx = fmaxf(fmaxf(s1r[r][0], s1r[r][1]), fmaxf(s1r[r][2], s1r[r][3]));
#pragma unroll
            for (int o = 8; o; o >>= 1) mx = fmaxf(mx, __shfl_xor_sync(0xffffffffu, mx, o));
            float mn = fmaxf(m1[r], mx);
            float corr = __expf(m1[r] - mn);
            float p[4], psum = 0.f;
#pragma unroll
            for (int c = 0; c < 4; c++) { p[c] = __expf(s1r[r][c] - mn); psum += p[c]; }
#pragma unroll
            for (int o = 8; o; o >>= 1) psum += __shfl_xor_sync(0xffffffffu, psum, o);
            l1[r] = l1[r] * corr + psum;
            m1[r] = mn;
            {
                ull cd = pk2(corr, corr);
#pragma unroll
                for (int j = 0; j < 4; j++) fmul2(o1[r][j], cd);
            }
#pragma unroll
            for (int c = 0; c < 4; c++) Ps1[q * PPAD + tx + 16 * c] = p[c];

            mx = fmaxf(fmaxf(s2r[r][0], s2r[r][1]), fmaxf(s2r[r][2], s2r[r][3]));
#pragma unroll
            for (int o = 8; o; o >>= 1) mx = fmaxf(mx, __shfl_xor_sync(0xffffffffu, mx, o));
            mn = fmaxf(m2[r], mx);
            corr = __expf(m2[r] - mn);
            psum = 0.f;
#pragma unroll
            for (int c = 0; c < 4; c++) { p[c] = __expf(s2r[r][c] - mn); psum += p[c]; }
#pragma unroll
            for (int o = 8; o; o >>= 1) psum += __shfl_xor_sync(0xffffffffu, psum, o);
            l2[r] = l2[r] * corr + psum;
            m2[r] = mn;
            {
                ull cd = pk2(corr, corr);
#pragma unroll
                for (int j = 0; j < 4; j++) fmul2(o2[r][j], cd);
            }
#pragma unroll
            for (int c = 0; c < 4; c++) Ps2[q * PPAD + tx + 16 * c] = p[c];
        }
        __syncthreads();

#pragma unroll 4
        for (int n = 0; n < 64; n++) {
            const float* vrow = &Vs[n * FPAD + 2 * tx];
            ull v0 = *(const ull*)(vrow);
            ull v1 = *(const ull*)(vrow + 32);
            ull v2 = *(const ull*)(vrow + 64);
            ull v3 = *(const ull*)(vrow + 96);
#pragma unroll
            for (int r = 0; r < 2; r++) {
                const int q = ty + 32 * r;
                float p1 = Ps1[q * PPAD + n];
                float p2 = Ps2[q * PPAD + n];
                ull p1d = pk2(p1, p1), p2d = pk2(p2, p2);
                ffma2(o1[r][0], p1d, v0); ffma2(o1[r][1], p1d, v1);
                ffma2(o1[r][2], p1d, v2); ffma2(o1[r][3], p1d, v3);
                ffma2(o2[r][0], p2d, v0); ffma2(o2[r][1], p2d, v1);
                ffma2(o2[r][2], p2d, v2); ffma2(o2[r][3], p2d, v3);
            }
        }
    }

#pragma unroll
    for (int r = 0; r < 2; r++) {
        float inv1 = 1.0f / l1[r];
        float sc2 = lam / l2[r];
        float cv8[8];
        float ss = 0.f;
#pragma unroll
        for (int cc = 0; cc < 4; cc++) {
            float2 a = upk2(o1[r][cc]);
            float2 bb = upk2(o2[r][cc]);
            float u = a.x * inv1 - bb.x * sc2;
            float w = a.y * inv1 - bb.y * sc2;
            cv8[2 * cc] = u; cv8[2 * cc + 1] = w;
            ss += u * u + w * w;
        }
#pragma unroll
        for (int o = 8; o; o >>= 1) ss += __shfl_xor_sync(0xffffffffu, ss, o);
        float rms = rsqrtf(ss * (1.0f / 128.0f) + 1e-5f);
        int sg = qs0 + ty + 32 * r;
        float* op = g_attn + (long)b * (SEQ * DMODEL) + h * (SEQ * HDIM) + sg * HDIM;
#pragma unroll
        for (int cc = 0; cc < 4; cc++) {
            int cvx = 2 * tx + 32 * cc;
            float2 w2;
            w2.x = cv8[2 * cc] * rms * subln[cvx] * 0.8f;
            w2.y = cv8[2 * cc + 1] * rms * subln[cvx + 1] * 0.8f;
            *(float2*)(op + cvx) = w2;
        }
    }
}

// ---------------- launch -----------------------------------------------------
extern "C" void kernel_launch(void* const* d_in, const int* in_sizes, int n_in,
                              void* d_out, int out_size) {
    const float* x    = (const float*)d_in[0];
    const float* fc   = (const float*)d_in[1];
    const float* w_in[4] = {(const float*)d_in[2], (const float*)d_in[3],
                            (const float*)d_in[4], (const float*)d_in[5]};
    const float* lq1  = (const float*)d_in[6];
    const float* lk1  = (const float*)d_in[7];
    const float* lq2  = (const float*)d_in[8];
    const float* lk2  = (const float*)d_in[9];
    const float* subw = (const float*)d_in[10];
    float* out = (float*)d_out;

    float *xq_p, *xk_p, *xv_p, *attn_p;
    __nv_bfloat16 *xhi, *xlo, *ahi, *alo, *whi, *wlo;
    cudaGetSymbolAddress((void**)&xq_p, g_xq);
    cudaGetSymbolAddress((void**)&xk_p, g_xk);
    cudaGetSymbolAddress((void**)&xv_p, g_xv);
    cudaGetSymbolAddress((void**)&attn_p, g_attn);
    cudaGetSymbolAddress((void**)&xhi, g_xhi);
    cudaGetSymbolAddress((void**)&xlo, g_xlo);
    cudaGetSymbolAddress((void**)&ahi, g_ahi);
    cudaGetSymbolAddress((void**)&alo, g_alo);
    cudaGetSymbolAddress((void**)&whi, g_whi);
    cudaGetSymbolAddress((void**)&wlo, g_wlo);

    const int NX = BATCH * SEQ * DMODEL;      // 8388608
    const int NW = DMODEL * DMODEL;           // 4194304

    split_bf16<<<NX / 1024, 256>>>(x, xhi, xlo, NX);
    for (int w = 0; w < 4; w++)
        split_bf16<<<NW / 1024, 256>>>(w_in[w], whi + (size_t)w * NW, wlo + (size_t)w * NW, NW);

    cudaFuncSetAttribute(gemm_mma, cudaFuncAttributeMaxDynamicSharedMemorySize, GEMM_SMEM);

    {
        GemmB bq = {whi + 0 * (size_t)NW, wlo + 0 * (size_t)NW, xq_p};
        GemmB bk = {whi + 1 * (size_t)NW, wlo + 1 * (size_t)NW, xk_p};
        GemmB bv = {whi + 2 * (size_t)NW, wlo + 2 * (size_t)NW, xv_p};
        gemm_mma<<<dim3(DMODEL / 128, (BATCH * SEQ) / 128, 3), 256, GEMM_SMEM>>>(
            xhi, xlo, bq, bk, bv);
    }

    rope_kernel<<<dim3((BATCH * SEQ * NHEADS * HHDIM) / 256, 2), 256>>>(fc);
    lambda_kernel<<<1, 32>>>(lq1, lk1, lq2, lk2);

    cudaFuncSetAttribute(flash_diff, cudaFuncAttributeMaxDynamicSharedMemorySize,
                         FSM_FLOATS * 4);
    flash_diff<<<dim3(SEQ / 64, BATCH * NHEADS), 512, FSM_FLOATS * 4>>>(subw);

    split_bf16<<<NX / 1024, 256>>>(attn_p, ahi, alo, NX);
    {
        GemmB bo = {whi + 3 * (size_t)NW, wlo + 3 * (size_t)NW, out};
        gemm_mma<<<dim3(DMODEL / 128, (BATCH * SEQ) / 128, 1), 256, GEMM_SMEM>>>(
            ahi, alo, bo, bo, bo);
    }
}

// round 11
// speedup vs baseline: 1.5285x; 1.0543x over previous
#include <cuda_runtime.h>
#include <cuda_bf16.h>
#include <cstdint>

#define BATCH 2
#define SEQ 2048
#define DMODEL 2048
#define NHEADS 16
#define HDIM 128
#define HHDIM 64

typedef unsigned long long ull;

// ---------------- scratch (device globals: no allocations allowed) -----------
__device__ float g_xq[BATCH * SEQ * NHEADS * HDIM];
__device__ float g_xk[BATCH * SEQ * NHEADS * HDIM];
__device__ float g_xv[BATCH * SEQ * NHEADS * HDIM];
__device__ float g_attn[BATCH * SEQ * DMODEL];        // scrambled (b,h,s,d) layout
__device__ float g_lambda;

// bf16 split buffers
__device__ __nv_bfloat16 g_xhi[BATCH * SEQ * DMODEL];
__device__ __nv_bfloat16 g_xlo[BATCH * SEQ * DMODEL];
__device__ __nv_bfloat16 g_ahi[BATCH * SEQ * DMODEL];
__device__ __nv_bfloat16 g_alo[BATCH * SEQ * DMODEL];
__device__ __nv_bfloat16 g_whi[4][DMODEL * DMODEL];   // q,k,v,o
__device__ __nv_bfloat16 g_wlo[4][DMODEL * DMODEL];

// ---------------- packed f32x2 helpers ---------------------------------------
__device__ __forceinline__ ull pk2(float lo, float hi) {
    ull r; asm("mov.b64 %0, {%1,%2};" : "=l"(r) : "f"(lo), "f"(hi)); return r;
}
__device__ __forceinline__ void ffma2(ull& d, ull a, ull b) {
    asm("fma.rn.f32x2 %0, %1, %2, %0;" : "+l"(d) : "l"(a), "l"(b));
}
__device__ __forceinline__ void fmul2(ull& d, ull b) {
    asm("mul.rn.f32x2 %0, %0, %1;" : "+l"(d) : "l"(b));
}
__device__ __forceinline__ float2 upk2(ull v) {
    float2 f; asm("mov.b64 {%0,%1}, %2;" : "=f"(f.x), "=f"(f.y) : "l"(v)); return f;
}

// ---------------- warp-MMA / async-copy helpers (baseline PTX, no 'a' feats) -
__device__ __forceinline__ uint32_t smem_u32(const void* p) {
    uint32_t a;
    asm("{ .reg .u64 t; cvta.to.shared.u64 t, %1; cvt.u32.u64 %0, t; }" : "=r"(a) : "l"(p));
    return a;
}
__device__ __forceinline__ void ldsm4(uint32_t* r, uint32_t addr) {
    asm volatile("ldmatrix.sync.aligned.m8n8.x4.shared.b16 {%0,%1,%2,%3}, [%4];"
                 : "=r"(r[0]), "=r"(r[1]), "=r"(r[2]), "=r"(r[3]) : "r"(addr));
}
__device__ __forceinline__ void mma16816(float* c, const uint32_t* a,
                                         uint32_t b0, uint32_t b1) {
    asm volatile("mma.sync.aligned.m16n8k16.row.col.f32.bf16.bf16.f32 "
                 "{%0,%1,%2,%3}, {%4,%5,%6,%7}, {%8,%9}, {%0,%1,%2,%3};"
                 : "+f"(c[0]), "+f"(c[1]), "+f"(c[2]), "+f"(c[3])
                 : "r"(a[0]), "r"(a[1]), "r"(a[2]), "r"(a[3]), "r"(b0), "r"(b1));
}
__device__ __forceinline__ void cp16(uint32_t saddr, const void* g) {
    asm volatile("cp.async.cg.shared.global [%0], [%1], 16;" :: "r"(saddr), "l"(g));
}
__device__ __forceinline__ void cp_commit() { asm volatile("cp.async.commit_group;"); }
__device__ __forceinline__ void cp_wait1()  { asm volatile("cp.async.wait_group 1;" ::: "memory"); }
__device__ __forceinline__ void cp_wait0()  { asm volatile("cp.async.wait_group 0;" ::: "memory"); }

// ---------------- bf16 hi/lo split -------------------------------------------
__global__ void split_bf16(const float* __restrict__ src, __nv_bfloat16* __restrict__ hi,
                           __nv_bfloat16* __restrict__ lo, int n) {
    int i = (blockIdx.x * blockDim.x + threadIdx.x) * 4;
    if (i >= n) return;
    float4 v = *(const float4*)(src + i);
    __nv_bfloat16 h0 = __float2bfloat16(v.x), h1 = __float2bfloat16(v.y);
    __nv_bfloat16 h2 = __float2bfloat16(v.z), h3 = __float2bfloat16(v.w);
    __nv_bfloat16 l0 = __float2bfloat16(v.x - __bfloat162float(h0));
    __nv_bfloat16 l1 = __float2bfloat16(v.y - __bfloat162float(h1));
    __nv_bfloat16 l2 = __float2bfloat16(v.z - __bfloat162float(h2));
    __nv_bfloat16 l3 = __float2bfloat16(v.w - __bfloat162float(h3));
    uint2 hp, lp;
    hp.x = (uint32_t)__bfloat16_as_ushort(h0) | ((uint32_t)__bfloat16_as_ushort(h1) << 16);
    hp.y = (uint32_t)__bfloat16_as_ushort(h2) | ((uint32_t)__bfloat16_as_ushort(h3) << 16);
    lp.x = (uint32_t)__bfloat16_as_ushort(l0) | ((uint32_t)__bfloat16_as_ushort(l1) << 16);
    lp.y = (uint32_t)__bfloat16_as_ushort(l2) | ((uint32_t)__bfloat16_as_ushort(l3) << 16);
    *(uint2*)(hi + i) = hp;
    *(uint2*)(lo + i) = lp;
}

// ---------------- split-bf16 HMMA GEMM ---------------------------------------
// Y[4096, 2048] = A[4096, 2048] @ W[2048, 2048]^T via (hi+lo) bf16, 3 products.
// CTA 128x128, 8 warps (2M x 4N), warp tile 64x32. K chunk = 32.
// 2-stage cp.async double buffer, 2 CTAs/SM for cross-CTA latency hiding.
#define TSTR 80                      // padded bytes per 32-bf16 row (bank-safe)
#define BUF_BYTES (128 * TSTR)       // 10240
#define STG_BYTES (4 * BUF_BYTES)    // Ahi,Alo,Bhi,Blo = 40960
#define NSTG 2
#define GEMM_SMEM (NSTG * STG_BYTES) // 81920
#define NCH (DMODEL / 32)            // 64 k-chunks

struct GemmB { const __nv_bfloat16* bhi; const __nv_bfloat16* blo; float* y; };

__global__ __launch_bounds__(256, 2)
void gemm_mma(const __nv_bfloat16* __restrict__ Ahi, const __nv_bfloat16* __restrict__ Alo,
              GemmB b0, GemmB b1, GemmB b2) {
    extern __shared__ char smem[];
    const uint32_t sb = smem_u32(smem);
    const int tid = threadIdx.x, wid = tid >> 5, lane = tid & 31;
    const int n0 = blockIdx.x * 128, m0 = blockIdx.y * 128;
    GemmB g = (blockIdx.z == 0) ? b0 : ((blockIdx.z == 1) ? b1 : b2);

    const __nv_bfloat16* srcs[4] = {
        Ahi + (size_t)m0 * DMODEL, Alo + (size_t)m0 * DMODEL,
        g.bhi + (size_t)n0 * DMODEL, g.blo + (size_t)n0 * DMODEL};

    // loader mapping: 512 16B-transfers per buffer, 2 per thread
    const int lrow0 = tid >> 2, lch = tid & 3;       // +64 rows for i=1

    float acc[4][4][4];
#pragma unroll
    for (int mt = 0; mt < 4; mt++)
#pragma unroll
        for (int nt = 0; nt < 4; nt++)
#pragma unroll
            for (int j = 0; j < 4; j++) acc[mt][nt][j] = 0.f;

    // prologue: chunk 0 -> stage 0
    {
        uint32_t stb = sb;
#pragma unroll
        for (int buf = 0; buf < 4; buf++) {
#pragma unroll
            for (int i = 0; i < 2; i++) {
                int row = lrow0 + i * 64;
                cp16(stb + buf * BUF_BYTES + row * TSTR + lch * 16,
                     srcs[buf] + (size_t)row * DMODEL + lch * 8);
            }
        }
        cp_commit();
    }

    const int wm = wid >> 2, wn = wid & 3;
    const int l7 = lane & 7, l8 = (lane >> 3) & 1, l16 = lane >> 4;
    const int lrow = l7 + l8 * 8;
    const int arow_base = wm * 64 + lrow;           // + mt*16
    const int brow_base = wn * 32 + lrow;           // + p*16

    for (int c = 0; c < NCH; c++) {
        // prefetch chunk c+1 into the other stage, then wait for chunk c
        if (c + 1 < NCH) {
            uint32_t stb = sb + ((c + 1) & 1) * STG_BYTES;
#pragma unroll
            for (int buf = 0; buf < 4; buf++) {
#pragma unroll
                for (int i = 0; i < 2; i++) {
                    int row = lrow0 + i * 64;
                    cp16(stb + buf * BUF_BYTES + row * TSTR + lch * 16,
                         srcs[buf] + (size_t)row * DMODEL + (c + 1) * 32 + lch * 8);
                }
            }
            cp_commit();
            cp_wait1();
        } else {
            cp_wait0();
        }
        __syncthreads();

        const uint32_t stb = sb + (c & 1) * STG_BYTES;
#pragma unroll
        for (int ks = 0; ks < 2; ks++) {
            const int ch = ks * 2 + l16;            // lane's 16B chunk
            uint32_t bhi[2][4], blo[2][4];
#pragma unroll
            for (int p = 0; p < 2; p++) {
                uint32_t off = (brow_base + p * 16) * TSTR + ch * 16;
                ldsm4(bhi[p], stb + 2 * BUF_BYTES + off);
                ldsm4(blo[p], stb + 3 * BUF_BYTES + off);
            }
#pragma unroll
            for (int mt = 0; mt < 4; mt++) {
                uint32_t ahi[4], alo[4];
                uint32_t off = (arow_base + mt * 16) * TSTR + ch * 16;
                ldsm4(ahi, stb + 0 * BUF_BYTES + off);
                ldsm4(alo, stb + 1 * BUF_BYTES + off);
#pragma unroll
                for (int nt = 0; nt < 4; nt++) {
                    const int p = nt >> 1, od = nt & 1;
                    mma16816(acc[mt][nt], ahi, bhi[p][od], bhi[p][od + 2]);
                    mma16816(acc[mt][nt], ahi, blo[p][od], blo[p][od + 2]);
                    mma16816(acc[mt][nt], alo, bhi[p][od], bhi[p][od + 2]);
                }
            }
        }
        __syncthreads();
    }

    // epilogue
    const int erow = lane >> 2, ecol = (lane & 3) * 2;
#pragma unroll
    for (int mt = 0; mt < 4; mt++) {
#pragma unroll
        for (int nt = 0; nt < 4; nt++) {
            int rg = m0 + wm * 64 + mt * 16 + erow;
            int cg = n0 + wn * 32 + nt * 8 + ecol;
            *(float2*)(g.y + (size_t)rg * DMODEL + cg) =
                make_float2(acc[mt][nt][0], acc[mt][nt][1]);
            *(float2*)(g.y + (size_t)(rg + 8) * DMODEL + cg) =
                make_float2(acc[mt][nt][2], acc[mt][nt][3]);
        }
    }
}

// ---------------- RoPE (in-place on g_xq / g_xk) -----------------------------
__global__ void rope_kernel(const float* __restrict__ fc) {
    int idx = blockIdx.x * blockDim.x + threadIdx.x;
    const int NP = BATCH * SEQ * NHEADS * HHDIM;
    if (idx >= NP) return;
    float* buf = blockIdx.y ? g_xk : g_xq;
    int d2 = idx & 63;
    int h  = (idx >> 6) & 15;
    int s  = (idx >> 10) & 2047;
    int b  = idx >> 21;
    float* p = buf + (((b * SEQ + s) * NHEADS + h) << 7) + d2 * 2;
    const float* f = fc + s * 256 + d2 * 4;
    float e = p[0], o = p[1];
    p[0] = e * f[0] + o * f[1];
    p[1] = e * f[2] + o * f[3];
}

// ---------------- lambda scalar ---------------------------------------------
__global__ void lambda_kernel(const float* __restrict__ lq1, const float* __restrict__ lk1,
                              const float* __restrict__ lq2, const float* __restrict__ lk2) {
    int t = threadIdx.x;
    float s1 = lq1[t] * lk1[t] + lq1[t + 32] * lk1[t + 32];
    float s2 = lq2[t] * lk2[t] + lq2[t + 32] * lk2[t + 32];
#pragma unroll
    for (int o = 16; o; o >>= 1) {
        s1 += __shfl_xor_sync(0xffffffffu, s1, o);
        s2 += __shfl_xor_sync(0xffffffffu, s2, o);
    }
    if (t == 0) g_lambda = expf(s1) - expf(s2) + 0.2f;
}

// ---------------- differential flash attention (fp32, f32x2) -----------------
#define FPAD 132
#define PPAD 68
#define FSM_FLOATS (3 * 64 * FPAD + 2 * 64 * PPAD)

__global__ __launch_bounds__(512, 1)
void flash_diff(const float* __restrict__ subln) {
    extern __shared__ __align__(16) float sm[];
    float* Qs  = sm;
    float* Ks  = sm + 64 * FPAD;
    float* Vs  = sm + 2 * 64 * FPAD;
    float* Ps1 = sm + 3 * 64 * FPAD;
    float* Ps2 = Ps1 + 64 * PPAD;

    const int tid = threadIdx.x;
    const int tx = tid & 15, ty = tid >> 4;
    const int qt = blockIdx.x, bh = blockIdx.y;
    const int b = bh >> 4, h = bh & 15;
    const int base = (b * SEQ * NHEADS + h) * HDIM;
    const float* Qg = g_xq + base;
    const float* Kg = g_xk + base;
    const float* Vg = g_xv + base;
    const int qs0 = qt * 64;
    const float lam = g_lambda;

    for (int i = tid; i < 2048; i += 512) {
        int row = i >> 5, d4 = (i & 31) << 2;
        float4 v = *(const float4*)(Qg + (qs0 + row) * 2048 + d4);
        v.x *= 0.125f; v.y *= 0.125f; v.z *= 0.125f; v.w *= 0.125f;
        *(float4*)&Qs[row * FPAD + d4] = v;
    }

    float m1[2] = {-1e30f, -1e30f}, l1[2] = {0.f, 0.f};
    float m2[2] = {-1e30f, -1e30f}, l2[2] = {0.f, 0.f};
    ull o1[2][4], o2[2][4];
#pragma unroll
    for (int r = 0; r < 2; r++)
#pragma unroll
        for (int j = 0; j < 4; j++) { o1[r][j] = 0ull; o2[r][j] = 0ull; }

    for (int kt = 0; kt <= qt; kt++) {
        __syncthreads();
        for (int i = tid; i < 2048; i += 512) {
            int row = i >> 5, d4 = (i & 31) << 2;
            int gr = (kt * 64 + row) * 2048 + d4;
            *(float4*)&Ks[row * FPAD + d4] = *(const float4*)(Kg + gr);
            *(float4*)&Vs[row * FPAD + d4] = *(const float4*)(Vg + gr);
        }
        __syncthreads();

        float s1r[2][4], s2r[2][4];
#pragma unroll
        for (int r = 0; r < 2; r++)
#pragma unroll
            for (int c = 0; c < 4; c++) { s1r[r][c] = 0.f; s2r[r][c] = 0.f; }

#pragma unroll
        for (int d4 = 0; d4 < 64; d4 += 4) {
            float4 qa[2], ka[4];
#pragma unroll
            for (int r = 0; r < 2; r++) qa[r] = *(const float4*)&Qs[(ty + 32 * r) * FPAD + d4];
#pragma unroll
            for (int c = 0; c < 4; c++) ka[c] = *(const float4*)&Ks[(tx + 16 * c) * FPAD + d4];
#pragma unroll
            for (int r = 0; r < 2; r++)
#pragma unroll
                for (int c = 0; c < 4; c++)
                    s1r[r][c] += qa[r].x * ka[c].x + qa[r].y * ka[c].y +
                                 qa[r].z * ka[c].z + qa[r].w * ka[c].w;
#pragma unroll
            for (int r = 0; r < 2; r++) qa[r] = *(const float4*)&Qs[(ty + 32 * r) * FPAD + 64 + d4];
#pragma unroll
            for (int c = 0; c < 4; c++) ka[c] = *(const float4*)&Ks[(tx + 16 * c) * FPAD + 64 + d4];
#pragma unroll
            for (int r = 0; r < 2; r++)
#pragma unroll
                for (int c = 0; c < 4; c++)
                    s2r[r][c] += qa[r].x * ka[c].x + qa[r].y * ka[c].y +
                                 qa[r].z * ka[c].z + qa[r].w * ka[c].w;
        }

        const bool diag = (kt == qt);
#pragma unroll
        for (int r = 0; r < 2; r++) {
            const int q = ty + 32 * r;
            if (diag) {
#pragma unroll
                for (int c = 0; c < 4; c++) {
                    if (tx + 16 * c > q) { s1r[r][c] = -1e30f; s2r[r][c] = -1e30f; }
                }
            }
            float mx = fmaxf(fmaxf(s1r[r][0], s1r[r][1]), fmaxf(s1r[r][2], s1r[r][3]));
#pragma unroll
            for (int o = 8; o; o >>= 1) mx = fmaxf(mx, __shfl_xor_sync(0xffffffffu, mx, o));
            float mn = fmaxf(m1[r], mx);
            float corr = __expf(m1[r] - mn);
            float p[4], psum = 0.f;
#pragma unroll
            for (int c = 0; c < 4; c++) { p[c] = __expf(s1r[r][c] - mn); psum += p[c]; }
#pragma unroll
            for (int o = 8; o; o >>= 1) psum += __shfl_xor_sync(0xffffffffu, psum, o);
            l1[r] = l1[r] * corr + psum;
            m1[r] = mn;
            {
                ull cd = pk2(corr, corr);
#pragma unroll
                for (int j = 0; j < 4; j++) fmul2(o1[r][j], cd);
            }
#pragma unroll
            for (int c = 0; c < 4; c++) Ps1[q * PPAD + tx + 16 * c] = p[c];

            mx = fmaxf(fmaxf(s2r[r][0], s2r[r][1]), fmaxf(s2r[r][2], s2r[r][3]));
#pragma unroll
            for (int o = 8; o; o >>= 1) mx = fmaxf(mx, __shfl_xor_sync(0xffffffffu, mx, o));
            mn = fmaxf(m2[r], mx);
            corr = __expf(m2[r] - mn);
            psum = 0.f;
#pragma unroll
            for (int c = 0; c < 4; c++) { p[c] = __expf(s2r[r][c] - mn); psum += p[c]; }
#pragma unroll
            for (int o = 8; o; o >>= 1) psum += __shfl_xor_sync(0xffffffffu, psum, o);
            l2[r] = l2[r] * corr + psum;
            m2[r] = mn;
            {
                ull cd = pk2(corr, corr);
#pragma unroll
                for (int j = 0; j < 4; j++) fmul2(o2[r][j], cd);
            }
#pragma unroll
            for (int c = 0; c < 4; c++) Ps2[q * PPAD + tx + 16 * c] = p[c];
        }
        __syncthreads();

#pragma unroll 4
        for (int n = 0; n < 64; n++) {
            const float* vrow = &Vs[n * FPAD + 2 * tx];
            ull v0 = *(const ull*)(vrow);
            ull v1 = *(const ull*)(vrow + 32);
            ull v2 = *(const ull*)(vrow + 64);
            ull v3 = *(const ull*)(vrow + 96);
#pragma unroll
            for (int r = 0; r < 2; r++) {
                const int q = ty + 32 * r;
                float p1 = Ps1[q * PPAD + n];
                float p2 = Ps2[q * PPAD + n];
                ull p1d = pk2(p1, p1), p2d = pk2(p2, p2);
                ffma2(o1[r][0], p1d, v0); ffma2(o1[r][1], p1d, v1);
                ffma2(o1[r][2], p1d, v2); ffma2(o1[r][3], p1d, v3);
                ffma2(o2[r][0], p2d, v0); ffma2(o2[r][1], p2d, v1);
                ffma2(o2[r][2], p2d, v2); ffma2(o2[r][3], p2d, v3);
            }
        }
    }

#pragma unroll
    for (int r = 0; r < 2; r++) {
        float inv1 = 1.0f / l1[r];
        float sc2 = lam / l2[r];
        float cv8[8];
        float ss = 0.f;
#pragma unroll
        for (int cc = 0; cc < 4; cc++) {
            float2 a = upk2(o1[r][cc]);
            float2 bb = upk2(o2[r][cc]);
            float u = a.x * inv1 - bb.x * sc2;
            float w = a.y * inv1 - bb.y * sc2;
            cv8[2 * cc] = u; cv8[2 * cc + 1] = w;
            ss += u * u + w * w;
        }
#pragma unroll
        for (int o = 8; o; o >>= 1) ss += __shfl_xor_sync(0xffffffffu, ss, o);
        float rms = rsqrtf(ss * (1.0f / 128.0f) + 1e-5f);
        int sg = qs0 + ty + 32 * r;
        float* op = g_attn + (long)b * (SEQ * DMODEL) + h * (SEQ * HDIM) + sg * HDIM;
#pragma unroll
        for (int cc = 0; cc < 4; cc++) {
            int cvx = 2 * tx + 32 * cc;
            float2 w2;
            w2.x = cv8[2 * cc] * rms * subln[cvx] * 0.8f;
            w2.y = cv8[2 * cc + 1] * rms * subln[cvx + 1] * 0.8f;
            *(float2*)(op + cvx) = w2;
        }
    }
}

// ---------------- launch -----------------------------------------------------
extern "C" void kernel_launch(void* const* d_in, const int* in_sizes, int n_in,
                              void* d_out, int out_size) {
    const float* x    = (const float*)d_in[0];
    const float* fc   = (const float*)d_in[1];
    const float* w_in[4] = {(const float*)d_in[2], (const float*)d_in[3],
                            (const float*)d_in[4], (const float*)d_in[5]};
    const float* lq1  = (const float*)d_in[6];
    const float* lk1  = (const float*)d_in[7];
    const float* lq2  = (const float*)d_in[8];
    const float* lk2  = (const float*)d_in[9];
    const float* subw = (const float*)d_in[10];
    float* out = (float*)d_out;

    float *xq_p, *xk_p, *xv_p, *attn_p;
    __nv_bfloat16 *xhi, *xlo, *ahi, *alo, *whi, *wlo;
    cudaGetSymbolAddress((void**)&xq_p, g_xq);
    cudaGetSymbolAddress((void**)&xk_p, g_xk);
    cudaGetSymbolAddress((void**)&xv_p, g_xv);
    cudaGetSymbolAddress((void**)&attn_p, g_attn);
    cudaGetSymbolAddress((void**)&xhi, g_xhi);
    cudaGetSymbolAddress((void**)&xlo, g_xlo);
    cudaGetSymbolAddress((void**)&ahi, g_ahi);
    cudaGetSymbolAddress((void**)&alo, g_alo);
    cudaGetSymbolAddress((void**)&whi, g_whi);
    cudaGetSymbolAddress((void**)&wlo, g_wlo);

    const int NX = BATCH * SEQ * DMODEL;      // 8388608
    const int NW = DMODEL * DMODEL;           // 4194304

    split_bf16<<<NX / 1024, 256>>>(x, xhi, xlo, NX);
    for (int w = 0; w < 4; w++)
        split_bf16<<<NW / 1024, 256>>>(w_in[w], whi + (size_t)w * NW, wlo + (size_t)w * NW, NW);

    cudaFuncSetAttribute(gemm_mma, cudaFuncAttributeMaxDynamicSharedMemorySize, GEMM_SMEM);

    {
        GemmB bq = {whi + 0 * (size_t)NW, wlo + 0 * (size_t)NW, xq_p};
        GemmB bk = {whi + 1 * (size_t)NW, wlo + 1 * (size_t)NW, xk_p};
        GemmB bv = {whi + 2 * (size_t)NW, wlo + 2 * (size_t)NW, xv_p};
        gemm_mma<<<dim3(DMODEL / 128, (BATCH * SEQ) / 128, 3), 256, GEMM_SMEM>>>(
            xhi, xlo, bq, bk, bv);
    }

    rope_kernel<<<dim3((BATCH * SEQ * NHEADS * HHDIM) / 256, 2), 256>>>(fc);
    lambda_kernel<<<1, 32>>>(lq1, lk1, lq2, lk2);

    cudaFuncSetAttribute(flash_diff, cudaFuncAttributeMaxDynamicSharedMemorySize,
                         FSM_FLOATS * 4);
    flash_diff<<<dim3(SEQ / 64, BATCH * NHEADS), 512, FSM_FLOATS * 4>>>(subw);

    split_bf16<<<NX / 1024, 256>>>(attn_p, ahi, alo, NX);
    {
        GemmB bo = {whi + 3 * (size_t)NW, wlo + 3 * (size_t)NW, out};
        gemm_mma<<<dim3(DMODEL / 128, (BATCH * SEQ) / 128, 1), 256, GEMM_SMEM>>>(
            ahi, alo, bo, bo, bo);
    }
}

// round 13
// speedup vs baseline: 2.3792x; 1.5566x over previous
#include <cuda_runtime.h>
#include <cuda_bf16.h>
#include <cstdint>

#define BATCH 2
#define SEQ 2048
#define DMODEL 2048
#define NHEADS 16
#define HDIM 128
#define HHDIM 64

typedef unsigned long long ull;

// ---------------- scratch (device globals: no allocations allowed) -----------
__device__ float g_xq[BATCH * SEQ * NHEADS * HDIM];
__device__ float g_xk[BATCH * SEQ * NHEADS * HDIM];
__device__ float g_xv[BATCH * SEQ * NHEADS * HDIM];
__device__ float g_lambda;

__device__ __nv_bfloat16 g_xhi[BATCH * SEQ * DMODEL];
__device__ __nv_bfloat16 g_xlo[BATCH * SEQ * DMODEL];
__device__ __nv_bfloat16 g_ahi[BATCH * SEQ * DMODEL];
__device__ __nv_bfloat16 g_alo[BATCH * SEQ * DMODEL];
__device__ __nv_bfloat16 g_whi[4][DMODEL * DMODEL];   // q,k,v,o
__device__ __nv_bfloat16 g_wlo[4][DMODEL * DMODEL];

// flash operands (bf16 hi/lo)
__device__ __nv_bfloat16 g_qhi[BATCH * SEQ * DMODEL];
__device__ __nv_bfloat16 g_qlo[BATCH * SEQ * DMODEL];
__device__ __nv_bfloat16 g_khi[BATCH * SEQ * DMODEL];
__device__ __nv_bfloat16 g_klo[BATCH * SEQ * DMODEL];
__device__ __nv_bfloat16 g_vhiT[BATCH * NHEADS * HDIM * SEQ];  // [bh][d][s]
__device__ __nv_bfloat16 g_vloT[BATCH * NHEADS * HDIM * SEQ];
__device__ float g_attn1[BATCH * NHEADS * SEQ * HDIM];         // [bh][s][d]
__device__ float g_attn2[BATCH * NHEADS * SEQ * HDIM];

// ---------------- helpers ----------------------------------------------------
__device__ __forceinline__ uint32_t smem_u32(const void* p) {
    uint32_t a;
    asm("{ .reg .u64 t; cvta.to.shared.u64 t, %1; cvt.u32.u64 %0, t; }" : "=r"(a) : "l"(p));
    return a;
}
__device__ __forceinline__ void ldsm4(uint32_t* r, uint32_t addr) {
    asm volatile("ldmatrix.sync.aligned.m8n8.x4.shared.b16 {%0,%1,%2,%3}, [%4];"
                 : "=r"(r[0]), "=r"(r[1]), "=r"(r[2]), "=r"(r[3]) : "r"(addr));
}
__device__ __forceinline__ void mma16816(float* c, const uint32_t* a,
                                         uint32_t b0, uint32_t b1) {
    asm volatile("mma.sync.aligned.m16n8k16.row.col.f32.bf16.bf16.f32 "
                 "{%0,%1,%2,%3}, {%4,%5,%6,%7}, {%8,%9}, {%0,%1,%2,%3};"
                 : "+f"(c[0]), "+f"(c[1]), "+f"(c[2]), "+f"(c[3])
                 : "r"(a[0]), "r"(a[1]), "r"(a[2]), "r"(a[3]), "r"(b0), "r"(b1));
}
__device__ __forceinline__ void cp16(uint32_t saddr, const void* g) {
    asm volatile("cp.async.cg.shared.global [%0], [%1], 16;" :: "r"(saddr), "l"(g));
}
__device__ __forceinline__ void cp_commit() { asm volatile("cp.async.commit_group;"); }
__device__ __forceinline__ void cp_wait1()  { asm volatile("cp.async.wait_group 1;" ::: "memory"); }
__device__ __forceinline__ void cp_wait0()  { asm volatile("cp.async.wait_group 0;" ::: "memory"); }
// pack two fp32 -> bf16x2 (lo = first arg), rne
__device__ __forceinline__ uint32_t packbf(float lo, float hi) {
    uint32_t r; asm("cvt.rn.bf16x2.f32 %0, %1, %2;" : "=r"(r) : "f"(hi), "f"(lo)); return r;
}
__device__ __forceinline__ float bflo(uint32_t v) { return __uint_as_float(v << 16); }
__device__ __forceinline__ float bfhi(uint32_t v) { return __uint_as_float(v & 0xffff0000u); }

// ---------------- bf16 hi/lo split -------------------------------------------
__global__ void split_bf16(const float* __restrict__ src, __nv_bfloat16* __restrict__ hi,
                           __nv_bfloat16* __restrict__ lo, int n) {
    int i = (blockIdx.x * blockDim.x + threadIdx.x) * 4;
    if (i >= n) return;
    float4 v = *(const float4*)(src + i);
    uint32_t h01 = packbf(v.x, v.y), h23 = packbf(v.z, v.w);
    uint32_t l01 = packbf(v.x - bflo(h01), v.y - bfhi(h01));
    uint32_t l23 = packbf(v.z - bflo(h23), v.w - bfhi(h23));
    *(uint2*)(hi + i) = make_uint2(h01, h23);
    *(uint2*)(lo + i) = make_uint2(l01, l23);
}

// ---------------- split-bf16 HMMA GEMM (round-11, proven) --------------------
#define TSTR 80
#define BUF_BYTES (128 * TSTR)
#define STG_BYTES (4 * BUF_BYTES)
#define NSTG 2
#define GEMM_SMEM (NSTG * STG_BYTES)
#define NCH (DMODEL / 32)

struct GemmB { const __nv_bfloat16* bhi; const __nv_bfloat16* blo; float* y; };

__global__ __launch_bounds__(256, 2)
void gemm_mma(const __nv_bfloat16* __restrict__ Ahi, const __nv_bfloat16* __restrict__ Alo,
              GemmB b0, GemmB b1, GemmB b2) {
    extern __shared__ char smem[];
    const uint32_t sb = smem_u32(smem);
    const int tid = threadIdx.x, wid = tid >> 5, lane = tid & 31;
    const int n0 = blockIdx.x * 128, m0 = blockIdx.y * 128;
    GemmB g = (blockIdx.z == 0) ? b0 : ((blockIdx.z == 1) ? b1 : b2);

    const __nv_bfloat16* srcs[4] = {
        Ahi + (size_t)m0 * DMODEL, Alo + (size_t)m0 * DMODEL,
        g.bhi + (size_t)n0 * DMODEL, g.blo + (size_t)n0 * DMODEL};

    const int lrow0 = tid >> 2, lch = tid & 3;

    float acc[4][4][4];
#pragma unroll
    for (int mt = 0; mt < 4; mt++)
#pragma unroll
        for (int nt = 0; nt < 4; nt++)
#pragma unroll
            for (int j = 0; j < 4; j++) acc[mt][nt][j] = 0.f;

    {
        uint32_t stb = sb;
#pragma unroll
        for (int buf = 0; buf < 4; buf++)
#pragma unroll
            for (int i = 0; i < 2; i++) {
                int row = lrow0 + i * 64;
                cp16(stb + buf * BUF_BYTES + row * TSTR + lch * 16,
                     srcs[buf] + (size_t)row * DMODEL + lch * 8);
            }
        cp_commit();
    }

    const int wm = wid >> 2, wn = wid & 3;
    const int lrow = (lane & 7) + ((lane >> 3) & 1) * 8;
    const int l16 = lane >> 4;
    const int arow_base = wm * 64 + lrow;
    const int brow_base = wn * 32 + lrow;

    for (int c = 0; c < NCH; c++) {
        if (c + 1 < NCH) {
            uint32_t stb = sb + ((c + 1) & 1) * STG_BYTES;
#pragma unroll
            for (int buf = 0; buf < 4; buf++)
#pragma unroll
                for (int i = 0; i < 2; i++) {
                    int row = lrow0 + i * 64;
                    cp16(stb + buf * BUF_BYTES + row * TSTR + lch * 16,
                         srcs[buf] + (size_t)row * DMODEL + (c + 1) * 32 + lch * 8);
                }
            cp_commit();
            cp_wait1();
        } else {
            cp_wait0();
        }
        __syncthreads();

        const uint32_t stb = sb + (c & 1) * STG_BYTES;
#pragma unroll
        for (int ks = 0; ks < 2; ks++) {
            const int ch = ks * 2 + l16;
            uint32_t bhi[2][4], blo[2][4];
#pragma unroll
            for (int p = 0; p < 2; p++) {
                uint32_t off = (brow_base + p * 16) * TSTR + ch * 16;
                ldsm4(bhi[p], stb + 2 * BUF_BYTES + off);
                ldsm4(blo[p], stb + 3 * BUF_BYTES + off);
            }
#pragma unroll
            for (int mt = 0; mt < 4; mt++) {
                uint32_t ahi[4], alo[4];
                uint32_t off = (arow_base + mt * 16) * TSTR + ch * 16;
                ldsm4(ahi, stb + 0 * BUF_BYTES + off);
                ldsm4(alo, stb + 1 * BUF_BYTES + off);
#pragma unroll
                for (int nt = 0; nt < 4; nt++) {
                    const int p = nt >> 1, od = nt & 1;
                    mma16816(acc[mt][nt], ahi, bhi[p][od], bhi[p][od + 2]);
                    mma16816(acc[mt][nt], ahi, blo[p][od], blo[p][od + 2]);
                    mma16816(acc[mt][nt], alo, bhi[p][od], bhi[p][od + 2]);
                }
            }
        }
        __syncthreads();
    }

    const int erow = lane >> 2, ecol = (lane & 3) * 2;
#pragma unroll
    for (int mt = 0; mt < 4; mt++)
#pragma unroll
        for (int nt = 0; nt < 4; nt++) {
            int rg = m0 + wm * 64 + mt * 16 + erow;
            int cg = n0 + wn * 32 + nt * 8 + ecol;
            *(float2*)(g.y + (size_t)rg * DMODEL + cg) =
                make_float2(acc[mt][nt][0], acc[mt][nt][1]);
            *(float2*)(g.y + (size_t)(rg + 8) * DMODEL + cg) =
                make_float2(acc[mt][nt][2], acc[mt][nt][3]);
        }
}

// ---------------- fused RoPE + scale + bf16 split (Q and K) ------------------
__global__ void rope_split_kernel(const float* __restrict__ fc) {
    int idx = blockIdx.x * blockDim.x + threadIdx.x;
    const int NP = BATCH * SEQ * NHEADS * HHDIM;
    if (idx >= NP) return;
    const float* buf;
    __nv_bfloat16 *dhi, *dlo;
    float scale;
    if (blockIdx.y == 0) { buf = g_xq; dhi = g_qhi; dlo = g_qlo; scale = 0.125f; }
    else                 { buf = g_xk; dhi = g_khi; dlo = g_klo; scale = 1.0f; }
    int d2 = idx & 63;
    int h  = (idx >> 6) & 15;
    int s  = (idx >> 10) & 2047;
    int b  = idx >> 21;
    size_t base = ((size_t)((b * SEQ + s) * NHEADS + h) << 7) + d2 * 2;
    const float* p = buf + base;
    const float* f = fc + s * 256 + d2 * 4;
    float e = p[0], o = p[1];
    float e2 = (e * f[0] + o * f[1]) * scale;
    float o2 = (e * f[2] + o * f[3]) * scale;
    uint32_t hp = packbf(e2, o2);
    uint32_t lp = packbf(e2 - bflo(hp), o2 - bfhi(hp));
    *(uint32_t*)(dhi + base) = hp;
    *(uint32_t*)(dlo + base) = lp;
}

// ---------------- V transpose + split:  [b][s][h][d] -> [bh][d][s] -----------
__global__ void vsplitT_kernel() {
    __shared__ float tile[32][33];
    int bh = blockIdx.z, b = bh >> 4, h = bh & 15;
    int stile = blockIdx.x, dt = blockIdx.y;
    int t = threadIdx.x, tr = t >> 5, tc = t & 31;
#pragma unroll
    for (int i = 0; i < 4; i++) {
        int sl = tr + i * 8;
        tile[sl][tc] = g_xv[(size_t)((b * SEQ + stile * 32 + sl) * NHEADS + h) * HDIM + dt * 32 + tc];
    }
    __syncthreads();
#pragma unroll
    for (int i = 0; i < 4; i++) {
        int dl = tr + i * 8;
        float v = tile[tc][dl];
        size_t dst = (size_t)bh * (HDIM * SEQ) + (size_t)(dt * 32 + dl) * SEQ + stile * 32 + tc;
        __nv_bfloat16 hv = __float2bfloat16(v);
        g_vhiT[dst] = hv;
        g_vloT[dst] = __float2bfloat16(v - __bfloat162float(hv));
    }
}

// ---------------- lambda scalar ---------------------------------------------
__global__ void lambda_kernel(const float* __restrict__ lq1, const float* __restrict__ lk1,
                              const float* __restrict__ lq2, const float* __restrict__ lk2) {
    int t = threadIdx.x;
    float s1 = lq1[t] * lk1[t] + lq1[t + 32] * lk1[t + 32];
    float s2 = lq2[t] * lk2[t] + lq2[t + 32] * lk2[t + 32];
#pragma unroll
    for (int o = 16; o; o >>= 1) {
        s1 += __shfl_xor_sync(0xffffffffu, s1, o);
        s2 += __shfl_xor_sync(0xffffffffu, s2, o);
    }
    if (t == 0) g_lambda = expf(s1) - expf(s2) + 0.2f;
}

// ---------------- HMMA differential flash attention --------------------------
// Grid: (16 q-blocks of 128, 32 bh, 2 streams). 256 thr = 8 warps, warp = m16.
// K tile: [64 seq][64 d] hi/lo; V tile: [128 d][64 seq] hi/lo (pre-transposed).
#define FTSTR 144                        // 64 bf16 = 128B + 16 pad
#define KT_B (64 * FTSTR)                // 9216
#define VT_B (128 * FTSTR)               // 18432
#define FSTG (2 * KT_B + 2 * VT_B)       // 55296
#define FLASH_SMEM (2 * FSTG)            // 110592

#define FLASH_LOAD_TILE(kt, s) do {                                              \
    uint32_t stg_ = sb + (s) * FSTG;                                             \
    for (int i_ = 0; i_ < 2; i_++) {                                             \
        int t_ = tid + i_ * 256; int row_ = t_ >> 3, ch_ = t_ & 7;               \
        size_t src_ = (size_t)((kt) * 64 + row_) * 2048 + ch_ * 8;               \
        cp16(stg_ + row_ * FTSTR + ch_ * 16, Kh + src_);                         \
        cp16(stg_ + KT_B + row_ * FTSTR + ch_ * 16, Kl + src_);                  \
    }                                                                            \
    for (int i_ = 0; i_ < 4; i_++) {                                             \
        int t_ = tid + i_ * 256; int row_ = t_ >> 3, ch_ = t_ & 7;               \
        size_t src_ = (size_t)row_ * 2048 + (kt) * 64 + ch_ * 8;                 \
        cp16(stg_ + 2 * KT_B + row_ * FTSTR + ch_ * 16, Vh + src_);              \
        cp16(stg_ + 2 * KT_B + VT_B + row_ * FTSTR + ch_ * 16, Vl + src_);       \
    }                                                                            \
    cp_commit();                                                                 \
} while (0)

__global__ __launch_bounds__(256, 1)
void flash_hmma() {
    extern __shared__ char fsm[];
    const uint32_t sb = smem_u32(fsm);
    const int tid = threadIdx.x, wid = tid >> 5, lane = tid & 31;
    const int qb = blockIdx.x, bh = blockIdx.y, st = blockIdx.z;
    const int b = bh >> 4, h = bh & 15;
    const int ntiles = 2 * qb + 2;

    const size_t qkbase = (size_t)b * (SEQ * DMODEL) + (size_t)h * HDIM + st * 64;
    const __nv_bfloat16* Qh = g_qhi + qkbase;
    const __nv_bfloat16* Ql = g_qlo + qkbase;
    const __nv_bfloat16* Kh = g_khi + qkbase;
    const __nv_bfloat16* Kl = g_klo + qkbase;
    const __nv_bfloat16* Vh = g_vhiT + (size_t)bh * (HDIM * SEQ);
    const __nv_bfloat16* Vl = g_vloT + (size_t)bh * (HDIM * SEQ);
    float* Og = (st == 0 ? g_attn1 : g_attn2) + (size_t)bh * (SEQ * HDIM);

    // prologue: Q tile (128 x 64) into stage0 V area; extract A-frags
#pragma unroll
    for (int i = 0; i < 4; i++) {
        int t = tid + i * 256;
        int row = t >> 3, ch = t & 7;
        size_t src = (size_t)(qb * 128 + row) * 2048 + ch * 8;
        cp16(sb + 2 * KT_B + row * FTSTR + ch * 16, Qh + src);
        cp16(sb + 2 * KT_B + VT_B + row * FTSTR + ch * 16, Ql + src);
    }
    cp_commit();
    cp_wait0();
    __syncthreads();

    const int lrow = (lane & 7) + ((lane >> 3) & 1) * 8;
    const int l16 = lane >> 4;

    uint32_t qh[4][4], ql[4][4];
#pragma unroll
    for (int ks = 0; ks < 4; ks++) {
        uint32_t off = (wid * 16 + lrow) * FTSTR + (ks * 2 + l16) * 16;
        ldsm4(qh[ks], sb + 2 * KT_B + off);
        ldsm4(ql[ks], sb + 2 * KT_B + VT_B + off);
    }
    __syncthreads();

    FLASH_LOAD_TILE(0, 0);

    float m0 = -1e30f, m1 = -1e30f, l0 = 0.f, l1 = 0.f;
    float oacc[16][4];
#pragma unroll
    for (int t = 0; t < 16; t++)
#pragma unroll
        for (int j = 0; j < 4; j++) oacc[t][j] = 0.f;

    const int r0g = qb * 128 + wid * 16 + (lane >> 2);
    const int colb = 2 * (lane & 3);

    for (int kt = 0; kt < ntiles; kt++) {
        if (kt + 1 < ntiles) { FLASH_LOAD_TILE(kt + 1, (kt + 1) & 1); cp_wait1(); }
        else cp_wait0();
        __syncthreads();
        const uint32_t stg = sb + (kt & 1) * FSTG;

        // ---- S = Q K^T (3-product) ----
        float sacc[8][4];
#pragma unroll
        for (int j = 0; j < 8; j++)
#pragma unroll
            for (int k = 0; k < 4; k++) sacc[j][k] = 0.f;
#pragma unroll
        for (int ks = 0; ks < 4; ks++) {
            uint32_t kh[4][4], kl[4][4];
#pragma unroll
            for (int p = 0; p < 4; p++) {
                uint32_t off = (p * 16 + lrow) * FTSTR + (ks * 2 + l16) * 16;
                ldsm4(kh[p], stg + off);
                ldsm4(kl[p], stg + KT_B + off);
            }
#pragma unroll
            for (int p = 0; p < 4; p++)
#pragma unroll
                for (int od = 0; od < 2; od++) {
                    float* s = sacc[p * 2 + od];
                    mma16816(s, qh[ks], kh[p][od], kh[p][od + 2]);
                    mma16816(s, qh[ks], kl[p][od], kl[p][od + 2]);
                    mma16816(s, ql[ks], kh[p][od], kh[p][od + 2]);
                }
        }

        // ---- causal mask (only near diagonal) ----
        if (kt >= 2 * qb) {
            int cb = kt * 64 + colb;
#pragma unroll
            for (int j = 0; j < 8; j++) {
                int c0 = cb + j * 8;
                if (c0 > r0g)     sacc[j][0] = -1e30f;
                if (c0 + 1 > r0g) sacc[j][1] = -1e30f;
                if (c0 > r0g + 8)     sacc[j][2] = -1e30f;
                if (c0 + 1 > r0g + 8) sacc[j][3] = -1e30f;
            }
        }

        // ---- online softmax ----
        float mx0 = -1e30f, mx1 = -1e30f;
#pragma unroll
        for (int j = 0; j < 8; j++) {
            mx0 = fmaxf(mx0, fmaxf(sacc[j][0], sacc[j][1]));
            mx1 = fmaxf(mx1, fmaxf(sacc[j][2], sacc[j][3]));
        }
        mx0 = fmaxf(mx0, __shfl_xor_sync(0xffffffffu, mx0, 1));
        mx0 = fmaxf(mx0, __shfl_xor_sync(0xffffffffu, mx0, 2));
        mx1 = fmaxf(mx1, __shfl_xor_sync(0xffffffffu, mx1, 1));
        mx1 = fmaxf(mx1, __shfl_xor_sync(0xffffffffu, mx1, 2));
        float mn0 = fmaxf(m0, mx0), mn1 = fmaxf(m1, mx1);
        float cr0 = __expf(m0 - mn0), cr1 = __expf(m1 - mn1);
        float ps0 = 0.f, ps1 = 0.f;
#pragma unroll
        for (int j = 0; j < 8; j++) {
            sacc[j][0] = __expf(sacc[j][0] - mn0); ps0 += sacc[j][0];
            sacc[j][1] = __expf(sacc[j][1] - mn0); ps0 += sacc[j][1];
            sacc[j][2] = __expf(sacc[j][2] - mn1); ps1 += sacc[j][2];
            sacc[j][3] = __expf(sacc[j][3] - mn1); ps1 += sacc[j][3];
        }
        ps0 += __shfl_xor_sync(0xffffffffu, ps0, 1);
        ps0 += __shfl_xor_sync(0xffffffffu, ps0, 2);
        ps1 += __shfl_xor_sync(0xffffffffu, ps1, 1);
        ps1 += __shfl_xor_sync(0xffffffffu, ps1, 2);
        l0 = l0 * cr0 + ps0; l1 = l1 * cr1 + ps1;
        m0 = mn0; m1 = mn1;
#pragma unroll
        for (int t = 0; t < 16; t++) {
            oacc[t][0] *= cr0; oacc[t][1] *= cr0;
            oacc[t][2] *= cr1; oacc[t][3] *= cr1;
        }

        // ---- P C-frags -> bf16 hi/lo A-frags ----
        uint32_t phf[4][4], plf[4][4];
#pragma unroll
        for (int j2 = 0; j2 < 4; j2++) {
            float* ta = sacc[2 * j2];
            float* tb = sacc[2 * j2 + 1];
            phf[j2][0] = packbf(ta[0], ta[1]);
            phf[j2][1] = packbf(ta[2], ta[3]);
            phf[j2][2] = packbf(tb[0], tb[1]);
            phf[j2][3] = packbf(tb[2], tb[3]);
            plf[j2][0] = packbf(ta[0] - bflo(phf[j2][0]), ta[1] - bfhi(phf[j2][0]));
            plf[j2][1] = packbf(ta[2] - bflo(phf[j2][1]), ta[3] - bfhi(phf[j2][1]));
            plf[j2][2] = packbf(tb[0] - bflo(phf[j2][2]), tb[1] - bfhi(phf[j2][2]));
            plf[j2][3] = packbf(tb[2] - bflo(phf[j2][3]), tb[3] - bfhi(phf[j2][3]));
        }

        // ---- O += P V (3-product) ----
#pragma unroll
        for (int ks = 0; ks < 4; ks++) {
            uint32_t vf[8][4];
#pragma unroll
            for (int p = 0; p < 8; p++)
                ldsm4(vf[p], stg + 2 * KT_B + (p * 16 + lrow) * FTSTR + (ks * 2 + l16) * 16);
#pragma unroll
            for (int p = 0; p < 8; p++)
#pragma unroll
                for (int od = 0; od < 2; od++) {
                    mma16816(oacc[p * 2 + od], phf[ks], vf[p][od], vf[p][od + 2]);
                    mma16816(oacc[p * 2 + od], plf[ks], vf[p][od], vf[p][od + 2]);
                }
#pragma unroll
            for (int p = 0; p < 8; p++)
                ldsm4(vf[p], stg + 2 * KT_B + VT_B + (p * 16 + lrow) * FTSTR + (ks * 2 + l16) * 16);
#pragma unroll
            for (int p = 0; p < 8; p++)
#pragma unroll
                for (int od = 0; od < 2; od++)
                    mma16816(oacc[p * 2 + od], phf[ks], vf[p][od], vf[p][od + 2]);
        }
        __syncthreads();
    }

    // ---- epilogue: normalize, store ----
    float i0 = 1.f / l0, i1 = 1.f / l1;
    float* orow0 = Og + (size_t)(qb * 128 + wid * 16 + (lane >> 2)) * HDIM;
    float* orow1 = orow0 + 8 * HDIM;
#pragma unroll
    for (int t = 0; t < 16; t++) {
        int col = t * 8 + colb;
        *(float2*)(orow0 + col) = make_float2(oacc[t][0] * i0, oacc[t][1] * i0);
        *(float2*)(orow1 + col) = make_float2(oacc[t][2] * i1, oacc[t][3] * i1);
    }
}

// ---------------- combine: diff + RMSNorm + subln + 0.8 + bf16 split ---------
__global__ void combine_kernel(const float* __restrict__ subln) {
    int row = blockIdx.x * 8 + (threadIdx.x >> 5);
    int lane = threadIdx.x & 31;
    size_t off = (size_t)row * HDIM + lane * 4;
    float lam = g_lambda;
    float4 x1 = *(const float4*)(g_attn1 + off);
    float4 x2 = *(const float4*)(g_attn2 + off);
    float v0 = x1.x - lam * x2.x;
    float v1 = x1.y - lam * x2.y;
    float v2 = x1.z - lam * x2.z;
    float v3 = x1.w - lam * x2.w;
    float ss = v0 * v0 + v1 * v1 + v2 * v2 + v3 * v3;
#pragma unroll
    for (int o = 16; o; o >>= 1) ss += __shfl_xor_sync(0xffffffffu, ss, o);
    float rms = rsqrtf(ss * (1.0f / 128.0f) + 1e-5f);
    const float4 sw = *(const float4*)(subln + lane * 4);
    v0 *= rms * sw.x * 0.8f;
    v1 *= rms * sw.y * 0.8f;
    v2 *= rms * sw.z * 0.8f;
    v3 *= rms * sw.w * 0.8f;
    uint32_t h01 = packbf(v0, v1), h23 = packbf(v2, v3);
    uint32_t l01 = packbf(v0 - bflo(h01), v1 - bfhi(h01));
    uint32_t l23 = packbf(v2 - bflo(h23), v3 - bfhi(h23));
    *(uint2*)(g_ahi + off) = make_uint2(h01, h23);
    *(uint2*)(g_alo + off) = make_uint2(l01, l23);
}

// ---------------- launch -----------------------------------------------------
extern "C" void kernel_launch(void* const* d_in, const int* in_sizes, int n_in,
                              void* d_out, int out_size) {
    const float* x    = (const float*)d_in[0];
    const float* fc   = (const float*)d_in[1];
    const float* w_in[4] = {(const float*)d_in[2], (const float*)d_in[3],
                            (const float*)d_in[4], (const float*)d_in[5]};
    const float* lq1  = (const float*)d_in[6];
    const float* lk1  = (const float*)d_in[7];
    const float* lq2  = (const float*)d_in[8];
    const float* lk2  = (const float*)d_in[9];
    const float* subw = (const float*)d_in[10];
    float* out = (float*)d_out;

    float *xq_p, *xk_p, *xv_p;
    __nv_bfloat16 *xhi, *xlo, *ahi, *alo, *whi, *wlo;
    cudaGetSymbolAddress((void**)&xq_p, g_xq);
    cudaGetSymbolAddress((void**)&xk_p, g_xk);
    cudaGetSymbolAddress((void**)&xv_p, g_xv);
    cudaGetSymbolAddress((void**)&xhi, g_xhi);
    cudaGetSymbolAddress((void**)&xlo, g_xlo);
    cudaGetSymbolAddress((void**)&ahi, g_ahi);
    cudaGetSymbolAddress((void**)&alo, g_alo);
    cudaGetSymbolAddress((void**)&whi, g_whi);
    cudaGetSymbolAddress((void**)&wlo, g_wlo);

    const int NX = BATCH * SEQ * DMODEL;      // 8388608
    const int NW = DMODEL * DMODEL;           // 4194304
    const int NP = BATCH * SEQ * NHEADS * HHDIM;  // 4194304

    split_bf16<<<NX / 1024, 256>>>(x, xhi, xlo, NX);
    for (int w = 0; w < 4; w++)
        split_bf16<<<NW / 1024, 256>>>(w_in[w], whi + (size_t)w * NW, wlo + (size_t)w * NW, NW);

    cudaFuncSetAttribute(gemm_mma, cudaFuncAttributeMaxDynamicSharedMemorySize, GEMM_SMEM);
    {
        GemmB bq = {whi + 0 * (size_t)NW, wlo + 0 * (size_t)NW, xq_p};
        GemmB bk = {whi + 1 * (size_t)NW, wlo + 1 * (size_t)NW, xk_p};
        GemmB bv = {whi + 2 * (size_t)NW, wlo + 2 * (size_t)NW, xv_p};
        gemm_mma<<<dim3(DMODEL / 128, (BATCH * SEQ) / 128, 3), 256, GEMM_SMEM>>>(
            xhi, xlo, bq, bk, bv);
    }

    rope_split_kernel<<<dim3(NP / 256, 2), 256>>>(fc);
    vsplitT_kernel<<<dim3(SEQ / 32, HDIM / 32, BATCH * NHEADS), 256>>>();
    lambda_kernel<<<1, 32>>>(lq1, lk1, lq2, lk2);

    cudaFuncSetAttribute(flash_hmma, cudaFuncAttributeMaxDynamicSharedMemorySize, FLASH_SMEM);
    flash_hmma<<<dim3(SEQ / 128, BATCH * NHEADS, 2), 256, FLASH_SMEM>>>();

    combine_kernel<<<(BATCH * NHEADS * SEQ) / 8, 256>>>(subw);

    {
        GemmB bo = {whi + 3 * (size_t)NW, wlo + 3 * (size_t)NW, out};
        gemm_mma<<<dim3(DMODEL / 128, (BATCH * SEQ) / 128, 1), 256, GEMM_SMEM>>>(
            ahi, alo, bo, bo, bo);
    }
}